// round 12
// baseline (speedup 1.0000x reference)
#include <cuda_runtime.h>
#include <cuda_fp16.h>
#include <cuda_bf16.h>

// ---------------------------------------------------------------------------
// HierarchicalConsistencyLoss:
//   diff = offset_inst - offset_tree          (coords cancels, never loaded)
//   per-tree sums of (diff, 1) for labels > 0; loss =
//   sum_t ||sum_t/c_t||^2 [c_t>=2]  /  #{t : c_t>=1}
//
// R11: PDL made real. R10's finalize measured 8.7us at 2% issue — pure
// launch latency exposed AFTER accum because, without an explicit trigger,
// the PDL secondary only launches when the primary completes. accum now
// calls cudaTriggerProgrammaticLaunchCompletion() after issuing its reds,
// so the finalize grid launches and spins in cudaGridDependencySynchronize
// WHILE accum's last wave runs; the sync still guarantees completion +
// visibility. Accum itself unchanged (33.8us floor, NREP=32, branch-free).
// ---------------------------------------------------------------------------

#define NBINS 1024   // T=1000 padded to power of two
#define NREP  32     // 32*1024*8B = 256KB, L2-resident
#define FIN_CTAS 128
#define FIN_THR  256
#define TREES_PER_CTA 8   // FIN_CTAS * TREES_PER_CTA = NBINS

// per-bin packed accumulator: .x = f16x2(sum_x,sum_y), .y = f16x2(sum_z,count)
// zero-initialized at module load; finalize re-zeroes after each use.
__device__ uint2 g_bins16[NREP * NBINS];
__device__ float g_tot;                  // cross-CTA partial (reset each use)
__device__ float g_cnt;
__device__ unsigned int g_ticket;

__device__ __forceinline__ void red_h2v2(uint2* p, float dx, float dy, float dz) {
    __half2 xy = __floats2half2_rn(dx, dy);
    __half2 zc = __floats2half2_rn(dz, 1.0f);
    asm volatile("red.global.add.noftz.v2.f16x2 [%0], {%1, %2};"
                 :: "l"(p),
                    "r"(*reinterpret_cast<unsigned int*>(&xy)),
                    "r"(*reinterpret_cast<unsigned int*>(&zc))
                 : "memory");
}

__global__ void __launch_bounds__(256)
accum_kernel(const float4* __restrict__ oi,   // offset_inst as float4 stream
             const float4* __restrict__ ot,   // offset_tree as float4 stream
             const int4*   __restrict__ lab,  // labels as int4 stream
             int nquad,                        // number of 4-point groups
             const float* __restrict__ oi_s,  // scalar views for the tail
             const float* __restrict__ ot_s,
             const int*   __restrict__ lab_s,
             int n)                            // total points
{
    int i = blockIdx.x * blockDim.x + threadIdx.x;
    // spread concurrently-resident warps across replicas
    int rep = ((blockIdx.x << 3) + (threadIdx.x >> 5)) & (NREP - 1);
    uint2* bins = g_bins16 + rep * NBINS;

    if (i < nquad) {
        // 4 points = 12 floats = 3 float4 per array + 1 int4 of labels
        float4 a0 = __ldcs(&oi[3 * i + 0]);
        float4 a1 = __ldcs(&oi[3 * i + 1]);
        float4 a2 = __ldcs(&oi[3 * i + 2]);
        float4 b0 = __ldcs(&ot[3 * i + 0]);
        float4 b1 = __ldcs(&ot[3 * i + 1]);
        float4 b2 = __ldcs(&ot[3 * i + 2]);
        int4 L  = __ldcs(&lab[i]);

        // branch-free: label 0 hits bin 0, which finalize ignores
        red_h2v2(&bins[L.x], a0.x - b0.x, a0.y - b0.y, a0.z - b0.z);
        red_h2v2(&bins[L.y], a0.w - b0.w, a1.x - b1.x, a1.y - b1.y);
        red_h2v2(&bins[L.z], a1.z - b1.z, a1.w - b1.w, a2.x - b2.x);
        red_h2v2(&bins[L.w], a2.y - b2.y, a2.z - b2.z, a2.w - b2.w);
    }
    // tail points (n % 4) — N=4M so empty in practice
    if (i == 0) {
        for (int p = nquad * 4; p < n; ++p) {
            int l = lab_s[p];
            red_h2v2(&g_bins16[l],
                     oi_s[3 * p + 0] - ot_s[3 * p + 0],
                     oi_s[3 * p + 1] - ot_s[3 * p + 1],
                     oi_s[3 * p + 2] - ot_s[3 * p + 2]);
        }
    }

    // Allow the PDL secondary (finalize) to launch now: its launch latency
    // overlaps this kernel's last wave. The secondary's
    // cudaGridDependencySynchronize() still waits for our completion.
    cudaTriggerProgrammaticLaunchCompletion();
}

// Full-width finalize: CTA c owns trees [8c, 8c+8). Thread tid=(r*8+j)
// loads replica r of tree 8c+j, zero-stores it, smem-combines per tree,
// CTA partial (tot,cnt) is atomically added to a global pair; last CTA
// (ticket) writes the output and resets state for the next graph replay.
__global__ void __launch_bounds__(FIN_THR)
finalize_kernel(float* __restrict__ out) {
    cudaGridDependencySynchronize();   // PDL: wait for accum + visibility

    __shared__ float4 s_part[FIN_THR];
    __shared__ float2 s_tree[TREES_PER_CTA];

    int tid = threadIdx.x;
    int r = tid >> 3;                  // replica 0..31
    int j = tid & 7;                   // local tree 0..7
    int t = blockIdx.x * TREES_PER_CTA + j;

    uint2 b = g_bins16[r * NBINS + t];
    g_bins16[r * NBINS + t] = make_uint2(0u, 0u);   // self-clean
    float2 xy = __half22float2(*reinterpret_cast<__half2*>(&b.x));
    float2 zc = __half22float2(*reinterpret_cast<__half2*>(&b.y));
    s_part[tid] = make_float4(xy.x, xy.y, zc.x, zc.y);
    __syncthreads();

    if (tid < TREES_PER_CTA) {
        float sx = 0.f, sy = 0.f, sz = 0.f, c = 0.f;
        #pragma unroll
        for (int rr = 0; rr < NREP; ++rr) {
            float4 p = s_part[rr * 8 + tid];
            sx += p.x; sy += p.y; sz += p.z; c += p.w;
        }
        float tot = 0.f, ntree = 0.f;
        int tree = blockIdx.x * TREES_PER_CTA + tid;
        if (tree >= 1 && tree < 1000) {  // label 0 = stuff; 1000.. padding
            if (c >= 1.f) ntree = 1.f;
            if (c >= 2.f) {
                float inv = 1.f / c;
                float mx = sx * inv, my = sy * inv, mz = sz * inv;
                tot = mx * mx + my * my + mz * mz;
            }
        }
        s_tree[tid] = make_float2(tot, ntree);
    }
    __syncthreads();

    if (tid == 0) {
        float T = 0.f, C = 0.f;
        #pragma unroll
        for (int k = 0; k < TREES_PER_CTA; ++k) {
            T += s_tree[k].x; C += s_tree[k].y;
        }
        // accumulate CTA partial into the global pair
        atomicAdd(&g_tot, T);
        atomicAdd(&g_cnt, C);
        __threadfence();
        unsigned int prev = atomicAdd(&g_ticket, 1u);
        if (prev == FIN_CTAS - 1) {
            __threadfence();  // acquire: order reads after final ticket
            float FT = atomicAdd(&g_tot, 0.f);   // L2-coherent read
            float FC = atomicAdd(&g_cnt, 0.f);
            out[0] = (FC > 0.f) ? (FT / FC) : 0.f;
            g_tot = 0.f;       // reset for next replay
            g_cnt = 0.f;
            g_ticket = 0u;
        }
    }
}

extern "C" void kernel_launch(void* const* d_in, const int* in_sizes, int n_in,
                              void* d_out, int out_size) {
    // metadata order: coords, offset_inst, offset_tree, tree_labels
    const float* oi_s  = (const float*)d_in[1];
    const float* ot_s  = (const float*)d_in[2];
    const int*   lab_s = (const int*)d_in[3];
    int n = in_sizes[3];

    int nquad  = n / 4;
    int blocks = (nquad + 255) / 256;
    if (blocks < 1) blocks = 1;

    accum_kernel<<<blocks, 256>>>((const float4*)oi_s, (const float4*)ot_s,
                                  (const int4*)lab_s, nquad,
                                  oi_s, ot_s, lab_s, n);

    // finalize with Programmatic Dependent Launch: launch overlaps accum's
    // last wave (trigger in accum); cudaGridDependencySynchronize() inside
    // orders the bin reads.
    cudaLaunchAttribute attrs[1];
    attrs[0].id = cudaLaunchAttributeProgrammaticStreamSerialization;
    attrs[0].val.programmaticStreamSerializationAllowed = 1;

    cudaLaunchConfig_t cfg = {};
    cfg.gridDim  = dim3(FIN_CTAS, 1, 1);
    cfg.blockDim = dim3(FIN_THR, 1, 1);
    cfg.dynamicSmemBytes = 0;
    cfg.stream = 0;
    cfg.attrs = attrs;
    cfg.numAttrs = 1;

    float* out = (float*)d_out;
    cudaLaunchKernelEx(&cfg, finalize_kernel, out);
}

// round 13
// speedup vs baseline: 1.0496x; 1.0496x over previous
#include <cuda_runtime.h>
#include <cuda_fp16.h>
#include <cuda_bf16.h>

// ---------------------------------------------------------------------------
// HierarchicalConsistencyLoss:
//   diff = offset_inst - offset_tree          (coords cancels, never loaded)
//   per-tree sums of (diff, 1) for labels > 0; loss =
//   sum_t ||sum_t/c_t||^2 [c_t>=2]  /  #{t : c_t>=1}
//
// R12: single-variable probe — NREP 32 -> 64. Model: accum (33.8us) and the
// ~7us post-accum tail are both bound by the 4M-op L2 atomic stream
// (L1tex wavefronts + LTS atomic ALU backlog). 16->32 replicas was worth
// 10us (per-address queuing); 64 halves any residue at 32. Everything
// else is frozen at the 41.0us best config: 4 pts/thread accum, branch-
// free f16x2 v2 reds, __ldcs streams, full-width PDL finalize with
// trigger, ticket combine, self-cleaning tables.
// ---------------------------------------------------------------------------

#define NBINS 1024   // T=1000 padded to power of two
#define NREP  64     // 64*1024*8B = 512KB, L2-resident
#define FIN_CTAS 128
#define FIN_THR  256
#define TREES_PER_CTA 8   // FIN_CTAS * TREES_PER_CTA = NBINS

// per-bin packed accumulator: .x = f16x2(sum_x,sum_y), .y = f16x2(sum_z,count)
// zero-initialized at module load; finalize re-zeroes after each use.
__device__ uint2 g_bins16[NREP * NBINS];
__device__ float g_tot;                  // cross-CTA partial (reset each use)
__device__ float g_cnt;
__device__ unsigned int g_ticket;

__device__ __forceinline__ void red_h2v2(uint2* p, float dx, float dy, float dz) {
    __half2 xy = __floats2half2_rn(dx, dy);
    __half2 zc = __floats2half2_rn(dz, 1.0f);
    asm volatile("red.global.add.noftz.v2.f16x2 [%0], {%1, %2};"
                 :: "l"(p),
                    "r"(*reinterpret_cast<unsigned int*>(&xy)),
                    "r"(*reinterpret_cast<unsigned int*>(&zc))
                 : "memory");
}

__global__ void __launch_bounds__(256)
accum_kernel(const float4* __restrict__ oi,   // offset_inst as float4 stream
             const float4* __restrict__ ot,   // offset_tree as float4 stream
             const int4*   __restrict__ lab,  // labels as int4 stream
             int nquad,                        // number of 4-point groups
             const float* __restrict__ oi_s,  // scalar views for the tail
             const float* __restrict__ ot_s,
             const int*   __restrict__ lab_s,
             int n)                            // total points
{
    int i = blockIdx.x * blockDim.x + threadIdx.x;
    // spread concurrently-resident warps across replicas
    int rep = ((blockIdx.x << 3) + (threadIdx.x >> 5)) & (NREP - 1);
    uint2* bins = g_bins16 + rep * NBINS;

    if (i < nquad) {
        // 4 points = 12 floats = 3 float4 per array + 1 int4 of labels
        float4 a0 = __ldcs(&oi[3 * i + 0]);
        float4 a1 = __ldcs(&oi[3 * i + 1]);
        float4 a2 = __ldcs(&oi[3 * i + 2]);
        float4 b0 = __ldcs(&ot[3 * i + 0]);
        float4 b1 = __ldcs(&ot[3 * i + 1]);
        float4 b2 = __ldcs(&ot[3 * i + 2]);
        int4 L  = __ldcs(&lab[i]);

        // branch-free: label 0 hits bin 0, which finalize ignores
        red_h2v2(&bins[L.x], a0.x - b0.x, a0.y - b0.y, a0.z - b0.z);
        red_h2v2(&bins[L.y], a0.w - b0.w, a1.x - b1.x, a1.y - b1.y);
        red_h2v2(&bins[L.z], a1.z - b1.z, a1.w - b1.w, a2.x - b2.x);
        red_h2v2(&bins[L.w], a2.y - b2.y, a2.z - b2.z, a2.w - b2.w);
    }
    // tail points (n % 4) — N=4M so empty in practice
    if (i == 0) {
        for (int p = nquad * 4; p < n; ++p) {
            int l = lab_s[p];
            red_h2v2(&g_bins16[l],
                     oi_s[3 * p + 0] - ot_s[3 * p + 0],
                     oi_s[3 * p + 1] - ot_s[3 * p + 1],
                     oi_s[3 * p + 2] - ot_s[3 * p + 2]);
        }
    }

    // Allow the PDL secondary (finalize) to launch; its launch/ramp
    // overlaps our last wave + the L2 atomic backlog drain.
    cudaTriggerProgrammaticLaunchCompletion();
}

// Full-width finalize: CTA c owns trees [8c, 8c+8). Thread tid=(r*8+j)
// folds replicas r and r+32 of tree 8c+j, zero-stores both, smem-combines
// per tree, CTA partial (tot,cnt) -> global pair; last CTA (ticket) writes
// the output and resets state for the next graph replay.
__global__ void __launch_bounds__(FIN_THR)
finalize_kernel(float* __restrict__ out) {
    cudaGridDependencySynchronize();   // PDL: wait for accum + visibility

    __shared__ float4 s_part[FIN_THR];
    __shared__ float2 s_tree[TREES_PER_CTA];

    int tid = threadIdx.x;
    int r = tid >> 3;                  // replica 0..31 (also handles r+32)
    int j = tid & 7;                   // local tree 0..7
    int t = blockIdx.x * TREES_PER_CTA + j;

    uint2 b0 = g_bins16[r * NBINS + t];
    uint2 b1 = g_bins16[(r + 32) * NBINS + t];
    g_bins16[r * NBINS + t]        = make_uint2(0u, 0u);   // self-clean
    g_bins16[(r + 32) * NBINS + t] = make_uint2(0u, 0u);
    float2 xy0 = __half22float2(*reinterpret_cast<__half2*>(&b0.x));
    float2 zc0 = __half22float2(*reinterpret_cast<__half2*>(&b0.y));
    float2 xy1 = __half22float2(*reinterpret_cast<__half2*>(&b1.x));
    float2 zc1 = __half22float2(*reinterpret_cast<__half2*>(&b1.y));
    s_part[tid] = make_float4(xy0.x + xy1.x, xy0.y + xy1.y,
                              zc0.x + zc1.x, zc0.y + zc1.y);
    __syncthreads();

    if (tid < TREES_PER_CTA) {
        float sx = 0.f, sy = 0.f, sz = 0.f, c = 0.f;
        #pragma unroll
        for (int rr = 0; rr < 32; ++rr) {
            float4 p = s_part[rr * 8 + tid];
            sx += p.x; sy += p.y; sz += p.z; c += p.w;
        }
        float tot = 0.f, ntree = 0.f;
        int tree = blockIdx.x * TREES_PER_CTA + tid;
        if (tree >= 1 && tree < 1000) {  // label 0 = stuff; 1000.. padding
            if (c >= 1.f) ntree = 1.f;
            if (c >= 2.f) {
                float inv = 1.f / c;
                float mx = sx * inv, my = sy * inv, mz = sz * inv;
                tot = mx * mx + my * my + mz * mz;
            }
        }
        s_tree[tid] = make_float2(tot, ntree);
    }
    __syncthreads();

    if (tid == 0) {
        float T = 0.f, C = 0.f;
        #pragma unroll
        for (int k = 0; k < TREES_PER_CTA; ++k) {
            T += s_tree[k].x; C += s_tree[k].y;
        }
        atomicAdd(&g_tot, T);
        atomicAdd(&g_cnt, C);
        __threadfence();
        unsigned int prev = atomicAdd(&g_ticket, 1u);
        if (prev == FIN_CTAS - 1) {
            __threadfence();  // acquire: order reads after final ticket
            float FT = atomicAdd(&g_tot, 0.f);   // L2-coherent read
            float FC = atomicAdd(&g_cnt, 0.f);
            out[0] = (FC > 0.f) ? (FT / FC) : 0.f;
            g_tot = 0.f;       // reset for next replay
            g_cnt = 0.f;
            g_ticket = 0u;
        }
    }
}

extern "C" void kernel_launch(void* const* d_in, const int* in_sizes, int n_in,
                              void* d_out, int out_size) {
    // metadata order: coords, offset_inst, offset_tree, tree_labels
    const float* oi_s  = (const float*)d_in[1];
    const float* ot_s  = (const float*)d_in[2];
    const int*   lab_s = (const int*)d_in[3];
    int n = in_sizes[3];

    int nquad  = n / 4;
    int blocks = (nquad + 255) / 256;
    if (blocks < 1) blocks = 1;

    accum_kernel<<<blocks, 256>>>((const float4*)oi_s, (const float4*)ot_s,
                                  (const int4*)lab_s, nquad,
                                  oi_s, ot_s, lab_s, n);

    cudaLaunchAttribute attrs[1];
    attrs[0].id = cudaLaunchAttributeProgrammaticStreamSerialization;
    attrs[0].val.programmaticStreamSerializationAllowed = 1;

    cudaLaunchConfig_t cfg = {};
    cfg.gridDim  = dim3(FIN_CTAS, 1, 1);
    cfg.blockDim = dim3(FIN_THR, 1, 1);
    cfg.dynamicSmemBytes = 0;
    cfg.stream = 0;
    cfg.attrs = attrs;
    cfg.numAttrs = 1;

    float* out = (float*)d_out;
    cudaLaunchKernelEx(&cfg, finalize_kernel, out);
}

// round 14
// speedup vs baseline: 1.1119x; 1.0594x over previous
#include <cuda_runtime.h>
#include <cuda_fp16.h>
#include <cuda_bf16.h>

// ---------------------------------------------------------------------------
// HierarchicalConsistencyLoss:
//   diff = offset_inst - offset_tree          (coords cancels, never loaded)
//   per-tree sums of (diff, 1) for labels > 0; loss =
//   sum_t ||sum_t/c_t||^2 [c_t>=2]  /  #{t : c_t>=1}
//
// R13: NREP ladder continues — 64 -> 128 (1MB, still L2-resident).
// Measured curve: NREP 16->32 = -10us, 32->64 = -1.6us (per-address L2
// atomic queuing, ~1/NREP law). Finalize is ramp-bound (2.6% issue), so
// folding 4 replicas per thread is free. Everything else frozen at the
// 39.4us best config.
// ---------------------------------------------------------------------------

#define NBINS 1024    // T=1000 padded to power of two
#define NREP  128     // 128*1024*8B = 1MB, L2-resident
#define FIN_CTAS 128
#define FIN_THR  256
#define TREES_PER_CTA 8   // FIN_CTAS * TREES_PER_CTA = NBINS

// per-bin packed accumulator: .x = f16x2(sum_x,sum_y), .y = f16x2(sum_z,count)
// zero-initialized at module load; finalize re-zeroes after each use.
__device__ uint2 g_bins16[NREP * NBINS];
__device__ float g_tot;                  // cross-CTA partial (reset each use)
__device__ float g_cnt;
__device__ unsigned int g_ticket;

__device__ __forceinline__ void red_h2v2(uint2* p, float dx, float dy, float dz) {
    __half2 xy = __floats2half2_rn(dx, dy);
    __half2 zc = __floats2half2_rn(dz, 1.0f);
    asm volatile("red.global.add.noftz.v2.f16x2 [%0], {%1, %2};"
                 :: "l"(p),
                    "r"(*reinterpret_cast<unsigned int*>(&xy)),
                    "r"(*reinterpret_cast<unsigned int*>(&zc))
                 : "memory");
}

__global__ void __launch_bounds__(256)
accum_kernel(const float4* __restrict__ oi,   // offset_inst as float4 stream
             const float4* __restrict__ ot,   // offset_tree as float4 stream
             const int4*   __restrict__ lab,  // labels as int4 stream
             int nquad,                        // number of 4-point groups
             const float* __restrict__ oi_s,  // scalar views for the tail
             const float* __restrict__ ot_s,
             const int*   __restrict__ lab_s,
             int n)                            // total points
{
    int i = blockIdx.x * blockDim.x + threadIdx.x;
    // spread concurrently-resident warps across all 128 replicas:
    // low 3 bits from warp id, high 4 bits mixed from block id
    int rep = ((blockIdx.x << 3) + (threadIdx.x >> 5) + ((blockIdx.x >> 4) << 6))
              & (NREP - 1);
    uint2* bins = g_bins16 + rep * NBINS;

    if (i < nquad) {
        // 4 points = 12 floats = 3 float4 per array + 1 int4 of labels
        float4 a0 = __ldcs(&oi[3 * i + 0]);
        float4 a1 = __ldcs(&oi[3 * i + 1]);
        float4 a2 = __ldcs(&oi[3 * i + 2]);
        float4 b0 = __ldcs(&ot[3 * i + 0]);
        float4 b1 = __ldcs(&ot[3 * i + 1]);
        float4 b2 = __ldcs(&ot[3 * i + 2]);
        int4 L  = __ldcs(&lab[i]);

        // branch-free: label 0 hits bin 0, which finalize ignores
        red_h2v2(&bins[L.x], a0.x - b0.x, a0.y - b0.y, a0.z - b0.z);
        red_h2v2(&bins[L.y], a0.w - b0.w, a1.x - b1.x, a1.y - b1.y);
        red_h2v2(&bins[L.z], a1.z - b1.z, a1.w - b1.w, a2.x - b2.x);
        red_h2v2(&bins[L.w], a2.y - b2.y, a2.z - b2.z, a2.w - b2.w);
    }
    // tail points (n % 4) — N=4M so empty in practice
    if (i == 0) {
        for (int p = nquad * 4; p < n; ++p) {
            int l = lab_s[p];
            red_h2v2(&g_bins16[l],
                     oi_s[3 * p + 0] - ot_s[3 * p + 0],
                     oi_s[3 * p + 1] - ot_s[3 * p + 1],
                     oi_s[3 * p + 2] - ot_s[3 * p + 2]);
        }
    }

    // Allow the PDL secondary (finalize) to launch; its launch/ramp
    // overlaps our last wave + the L2 atomic backlog drain.
    cudaTriggerProgrammaticLaunchCompletion();
}

// Full-width finalize: CTA c owns trees [8c, 8c+8). Thread tid=(r*8+j)
// folds replicas r, r+32, r+64, r+96 of tree 8c+j, zero-stores them,
// smem-combines per tree, CTA partial (tot,cnt) -> global pair; last CTA
// (ticket) writes the output and resets state for the next graph replay.
__global__ void __launch_bounds__(FIN_THR)
finalize_kernel(float* __restrict__ out) {
    cudaGridDependencySynchronize();   // PDL: wait for accum + visibility

    __shared__ float4 s_part[FIN_THR];
    __shared__ float2 s_tree[TREES_PER_CTA];

    int tid = threadIdx.x;
    int r = tid >> 3;                  // base replica 0..31
    int j = tid & 7;                   // local tree 0..7
    int t = blockIdx.x * TREES_PER_CTA + j;

    float sx = 0.f, sy = 0.f, sz = 0.f, c = 0.f;
    #pragma unroll
    for (int k = 0; k < 4; ++k) {
        int rr = r + k * 32;
        uint2 b = g_bins16[rr * NBINS + t];
        float2 xy = __half22float2(*reinterpret_cast<__half2*>(&b.x));
        float2 zc = __half22float2(*reinterpret_cast<__half2*>(&b.y));
        sx += xy.x; sy += xy.y; sz += zc.x; c += zc.y;
    }
    // self-clean after all loads
    #pragma unroll
    for (int k = 0; k < 4; ++k)
        g_bins16[(r + k * 32) * NBINS + t] = make_uint2(0u, 0u);

    s_part[tid] = make_float4(sx, sy, sz, c);
    __syncthreads();

    if (tid < TREES_PER_CTA) {
        float tx = 0.f, ty = 0.f, tz = 0.f, tc = 0.f;
        #pragma unroll
        for (int rr = 0; rr < 32; ++rr) {
            float4 p = s_part[rr * 8 + tid];
            tx += p.x; ty += p.y; tz += p.z; tc += p.w;
        }
        float tot = 0.f, ntree = 0.f;
        int tree = blockIdx.x * TREES_PER_CTA + tid;
        if (tree >= 1 && tree < 1000) {  // label 0 = stuff; 1000.. padding
            if (tc >= 1.f) ntree = 1.f;
            if (tc >= 2.f) {
                float inv = 1.f / tc;
                float mx = tx * inv, my = ty * inv, mz = tz * inv;
                tot = mx * mx + my * my + mz * mz;
            }
        }
        s_tree[tid] = make_float2(tot, ntree);
    }
    __syncthreads();

    if (tid == 0) {
        float T = 0.f, C = 0.f;
        #pragma unroll
        for (int k = 0; k < TREES_PER_CTA; ++k) {
            T += s_tree[k].x; C += s_tree[k].y;
        }
        atomicAdd(&g_tot, T);
        atomicAdd(&g_cnt, C);
        __threadfence();
        unsigned int prev = atomicAdd(&g_ticket, 1u);
        if (prev == FIN_CTAS - 1) {
            __threadfence();  // acquire: order reads after final ticket
            float FT = atomicAdd(&g_tot, 0.f);   // L2-coherent read
            float FC = atomicAdd(&g_cnt, 0.f);
            out[0] = (FC > 0.f) ? (FT / FC) : 0.f;
            g_tot = 0.f;       // reset for next replay
            g_cnt = 0.f;
            g_ticket = 0u;
        }
    }
}

extern "C" void kernel_launch(void* const* d_in, const int* in_sizes, int n_in,
                              void* d_out, int out_size) {
    // metadata order: coords, offset_inst, offset_tree, tree_labels
    const float* oi_s  = (const float*)d_in[1];
    const float* ot_s  = (const float*)d_in[2];
    const int*   lab_s = (const int*)d_in[3];
    int n = in_sizes[3];

    int nquad  = n / 4;
    int blocks = (nquad + 255) / 256;
    if (blocks < 1) blocks = 1;

    accum_kernel<<<blocks, 256>>>((const float4*)oi_s, (const float4*)ot_s,
                                  (const int4*)lab_s, nquad,
                                  oi_s, ot_s, lab_s, n);

    cudaLaunchAttribute attrs[1];
    attrs[0].id = cudaLaunchAttributeProgrammaticStreamSerialization;
    attrs[0].val.programmaticStreamSerializationAllowed = 1;

    cudaLaunchConfig_t cfg = {};
    cfg.gridDim  = dim3(FIN_CTAS, 1, 1);
    cfg.blockDim = dim3(FIN_THR, 1, 1);
    cfg.dynamicSmemBytes = 0;
    cfg.stream = 0;
    cfg.attrs = attrs;
    cfg.numAttrs = 1;

    float* out = (float*)d_out;
    cudaLaunchKernelEx(&cfg, finalize_kernel, out);
}

// round 15
// speedup vs baseline: 1.1167x; 1.0043x over previous
#include <cuda_runtime.h>
#include <cuda_fp16.h>
#include <cuda_bf16.h>

// ---------------------------------------------------------------------------
// HierarchicalConsistencyLoss:
//   diff = offset_inst - offset_tree          (coords cancels, never loaded)
//   per-tree sums of (diff, 1) for labels > 0; loss =
//   sum_t ||sum_t/c_t||^2 [c_t>=2]  /  #{t : c_t>=1}
//
// R14: NREP ladder continues — 128 -> 256 (2MB, still L2-resident).
// Measured curve: 16->32 = -10us, 32->64 = -1.6us, 64->128 = -2.2us
// (per-address L2 atomic queuing still binding). Finalize stays ramp-bound
// (4% issue), so folding 8 replicas per thread is free. Replica hash uses
// warp id for low bits + multiplicative block mix for the rest.
// ---------------------------------------------------------------------------

#define NBINS 1024    // T=1000 padded to power of two
#define NREP  256     // 256*1024*8B = 2MB, L2-resident
#define FIN_CTAS 128
#define FIN_THR  256
#define TREES_PER_CTA 8   // FIN_CTAS * TREES_PER_CTA = NBINS

// per-bin packed accumulator: .x = f16x2(sum_x,sum_y), .y = f16x2(sum_z,count)
// zero-initialized at module load; finalize re-zeroes after each use.
__device__ uint2 g_bins16[NREP * NBINS];
__device__ float g_tot;                  // cross-CTA partial (reset each use)
__device__ float g_cnt;
__device__ unsigned int g_ticket;

__device__ __forceinline__ void red_h2v2(uint2* p, float dx, float dy, float dz) {
    __half2 xy = __floats2half2_rn(dx, dy);
    __half2 zc = __floats2half2_rn(dz, 1.0f);
    asm volatile("red.global.add.noftz.v2.f16x2 [%0], {%1, %2};"
                 :: "l"(p),
                    "r"(*reinterpret_cast<unsigned int*>(&xy)),
                    "r"(*reinterpret_cast<unsigned int*>(&zc))
                 : "memory");
}

__global__ void __launch_bounds__(256)
accum_kernel(const float4* __restrict__ oi,   // offset_inst as float4 stream
             const float4* __restrict__ ot,   // offset_tree as float4 stream
             const int4*   __restrict__ lab,  // labels as int4 stream
             int nquad,                        // number of 4-point groups
             const float* __restrict__ oi_s,  // scalar views for the tail
             const float* __restrict__ ot_s,
             const int*   __restrict__ lab_s,
             int n)                            // total points
{
    int i = blockIdx.x * blockDim.x + threadIdx.x;
    // replica: warp id in low 3 bits (co-resident warps distinct),
    // multiplicative block mix in the upper bits (no aliasing mod 256)
    int rep = ((threadIdx.x >> 5) + blockIdx.x * 37) & (NREP - 1);
    uint2* bins = g_bins16 + rep * NBINS;

    if (i < nquad) {
        // 4 points = 12 floats = 3 float4 per array + 1 int4 of labels
        int base = 3 * i;
        float4 a0 = __ldcs(&oi[base + 0]);
        float4 a1 = __ldcs(&oi[base + 1]);
        float4 a2 = __ldcs(&oi[base + 2]);
        float4 b0 = __ldcs(&ot[base + 0]);
        float4 b1 = __ldcs(&ot[base + 1]);
        float4 b2 = __ldcs(&ot[base + 2]);
        int4 L  = __ldcs(&lab[i]);

        // branch-free: label 0 hits bin 0, which finalize ignores
        red_h2v2(&bins[L.x], a0.x - b0.x, a0.y - b0.y, a0.z - b0.z);
        red_h2v2(&bins[L.y], a0.w - b0.w, a1.x - b1.x, a1.y - b1.y);
        red_h2v2(&bins[L.z], a1.z - b1.z, a1.w - b1.w, a2.x - b2.x);
        red_h2v2(&bins[L.w], a2.y - b2.y, a2.z - b2.z, a2.w - b2.w);
    }
    // tail points (n % 4) — N=4M so empty in practice
    if (i == 0) {
        for (int p = nquad * 4; p < n; ++p) {
            int l = lab_s[p];
            red_h2v2(&g_bins16[l],
                     oi_s[3 * p + 0] - ot_s[3 * p + 0],
                     oi_s[3 * p + 1] - ot_s[3 * p + 1],
                     oi_s[3 * p + 2] - ot_s[3 * p + 2]);
        }
    }

    // Allow the PDL secondary (finalize) to launch; its launch/ramp
    // overlaps our last wave + the L2 atomic backlog drain.
    cudaTriggerProgrammaticLaunchCompletion();
}

// Full-width finalize: CTA c owns trees [8c, 8c+8). Thread tid=(r*8+j)
// folds replicas r + k*32 (k=0..7) of tree 8c+j, zero-stores them,
// smem-combines per tree, CTA partial (tot,cnt) -> global pair; last CTA
// (ticket) writes the output and resets state for the next graph replay.
__global__ void __launch_bounds__(FIN_THR)
finalize_kernel(float* __restrict__ out) {
    cudaGridDependencySynchronize();   // PDL: wait for accum + visibility

    __shared__ float4 s_part[FIN_THR];
    __shared__ float2 s_tree[TREES_PER_CTA];

    int tid = threadIdx.x;
    int r = tid >> 3;                  // base replica 0..31
    int j = tid & 7;                   // local tree 0..7
    int t = blockIdx.x * TREES_PER_CTA + j;

    float sx = 0.f, sy = 0.f, sz = 0.f, c = 0.f;
    #pragma unroll
    for (int k = 0; k < NREP / 32; ++k) {
        int rr = r + k * 32;
        uint2 b = g_bins16[rr * NBINS + t];
        float2 xy = __half22float2(*reinterpret_cast<__half2*>(&b.x));
        float2 zc = __half22float2(*reinterpret_cast<__half2*>(&b.y));
        sx += xy.x; sy += xy.y; sz += zc.x; c += zc.y;
    }
    // self-clean after all loads
    #pragma unroll
    for (int k = 0; k < NREP / 32; ++k)
        g_bins16[(r + k * 32) * NBINS + t] = make_uint2(0u, 0u);

    s_part[tid] = make_float4(sx, sy, sz, c);
    __syncthreads();

    if (tid < TREES_PER_CTA) {
        float tx = 0.f, ty = 0.f, tz = 0.f, tc = 0.f;
        #pragma unroll
        for (int rr = 0; rr < 32; ++rr) {
            float4 p = s_part[rr * 8 + tid];
            tx += p.x; ty += p.y; tz += p.z; tc += p.w;
        }
        float tot = 0.f, ntree = 0.f;
        int tree = blockIdx.x * TREES_PER_CTA + tid;
        if (tree >= 1 && tree < 1000) {  // label 0 = stuff; 1000.. padding
            if (tc >= 1.f) ntree = 1.f;
            if (tc >= 2.f) {
                float inv = 1.f / tc;
                float mx = tx * inv, my = ty * inv, mz = tz * inv;
                tot = mx * mx + my * my + mz * mz;
            }
        }
        s_tree[tid] = make_float2(tot, ntree);
    }
    __syncthreads();

    if (tid == 0) {
        float T = 0.f, C = 0.f;
        #pragma unroll
        for (int k = 0; k < TREES_PER_CTA; ++k) {
            T += s_tree[k].x; C += s_tree[k].y;
        }
        atomicAdd(&g_tot, T);
        atomicAdd(&g_cnt, C);
        __threadfence();
        unsigned int prev = atomicAdd(&g_ticket, 1u);
        if (prev == FIN_CTAS - 1) {
            __threadfence();  // acquire: order reads after final ticket
            float FT = atomicAdd(&g_tot, 0.f);   // L2-coherent read
            float FC = atomicAdd(&g_cnt, 0.f);
            out[0] = (FC > 0.f) ? (FT / FC) : 0.f;
            g_tot = 0.f;       // reset for next replay
            g_cnt = 0.f;
            g_ticket = 0u;
        }
    }
}

extern "C" void kernel_launch(void* const* d_in, const int* in_sizes, int n_in,
                              void* d_out, int out_size) {
    // metadata order: coords, offset_inst, offset_tree, tree_labels
    const float* oi_s  = (const float*)d_in[1];
    const float* ot_s  = (const float*)d_in[2];
    const int*   lab_s = (const int*)d_in[3];
    int n = in_sizes[3];

    int nquad  = n / 4;
    int blocks = (nquad + 255) / 256;
    if (blocks < 1) blocks = 1;

    accum_kernel<<<blocks, 256>>>((const float4*)oi_s, (const float4*)ot_s,
                                  (const int4*)lab_s, nquad,
                                  oi_s, ot_s, lab_s, n);

    cudaLaunchAttribute attrs[1];
    attrs[0].id = cudaLaunchAttributeProgrammaticStreamSerialization;
    attrs[0].val.programmaticStreamSerializationAllowed = 1;

    cudaLaunchConfig_t cfg = {};
    cfg.gridDim  = dim3(FIN_CTAS, 1, 1);
    cfg.blockDim = dim3(FIN_THR, 1, 1);
    cfg.dynamicSmemBytes = 0;
    cfg.stream = 0;
    cfg.attrs = attrs;
    cfg.numAttrs = 1;

    float* out = (float*)d_out;
    cudaLaunchKernelEx(&cfg, finalize_kernel, out);
}